// round 5
// baseline (speedup 1.0000x reference)
#include <cuda_runtime.h>
#include <cuda_bf16.h>
#include <cstdint>
#include <cstddef>

// ============================================================================
// GAT fusion, B=8192, N=12, D=256, SEL={0,3,6,9}.  sm_100 (no 'a' features):
// mma.sync.m16n8k16.bf16 with bf16x3 (hi*hi + hi*lo + lo*hi) fp32-grade GEMMs,
// cp.async 4-stage smem pipeline, semi-persistent blocks.
//
//   Wh1 = relu(h@Wv^T+bv); k1 = relu(h@Wk^T+bk)      (12 rows/batch)
//   q1  = relu(h_sel@Wq^T+bq)                         (4 rows/batch)
//   att = softmax(mask(q1.k1)) * label;  f1 = att@Wh1
//   out = f1 @ (Wf@Wo1)^T + (Wf@bo1+bf)               (folded affine)
// ============================================================================

#define BATCH   8192
#define NNODE   12
#define DIM     256
#define M_VK    (BATCH * NNODE)     // 98304
#define M_SEL   (BATCH * 4)         // 32768

// ---------------- scratch (device globals; no allocation) -------------------
__device__ __nv_bfloat16 g_hh[M_VK * DIM], g_hl[M_VK * DIM];   // h split
__device__ float g_Wh1[M_VK * DIM];
__device__ float g_k1 [M_VK * DIM];
__device__ float g_q1 [M_SEL * DIM];
__device__ __nv_bfloat16 g_f1h[M_SEL * DIM], g_f1l[M_SEL * DIM];
__device__ float g_bc [DIM];
__device__ __nv_bfloat16 g_Wv_h[DIM*DIM], g_Wv_l[DIM*DIM];
__device__ __nv_bfloat16 g_Wk_h[DIM*DIM], g_Wk_l[DIM*DIM];
__device__ __nv_bfloat16 g_Wq_h[DIM*DIM], g_Wq_l[DIM*DIM];
__device__ __nv_bfloat16 g_Wc_h[DIM*DIM], g_Wc_l[DIM*DIM];

// ---------------- helpers ----------------------------------------------------
__device__ __forceinline__ uint32_t smem_u32(const void* p) {
    return (uint32_t)__cvta_generic_to_shared(p);
}
__device__ __forceinline__ void ldmatrix_x4(uint32_t& r0, uint32_t& r1,
                                            uint32_t& r2, uint32_t& r3, uint32_t addr) {
    asm volatile("ldmatrix.sync.aligned.m8n8.x4.shared.b16 {%0,%1,%2,%3}, [%4];\n"
                 : "=r"(r0), "=r"(r1), "=r"(r2), "=r"(r3) : "r"(addr));
}
__device__ __forceinline__ void ldmatrix_x2(uint32_t& r0, uint32_t& r1, uint32_t addr) {
    asm volatile("ldmatrix.sync.aligned.m8n8.x2.shared.b16 {%0,%1}, [%2];\n"
                 : "=r"(r0), "=r"(r1) : "r"(addr));
}
__device__ __forceinline__ void mma_bf16(float c[4],
                                         uint32_t a0, uint32_t a1, uint32_t a2, uint32_t a3,
                                         uint32_t b0, uint32_t b1) {
    asm volatile("mma.sync.aligned.m16n8k16.row.col.f32.bf16.bf16.f32 "
                 "{%0,%1,%2,%3}, {%4,%5,%6,%7}, {%8,%9}, {%0,%1,%2,%3};\n"
                 : "+f"(c[0]), "+f"(c[1]), "+f"(c[2]), "+f"(c[3])
                 : "r"(a0), "r"(a1), "r"(a2), "r"(a3), "r"(b0), "r"(b1));
}
__device__ __forceinline__ void cp16(uint32_t dst, const void* src) {
    asm volatile("cp.async.cg.shared.global [%0], [%1], 16;\n" :: "r"(dst), "l"(src));
}

// ---------------- prologue kernels -------------------------------------------
__global__ void convert_w_kernel(const float* __restrict__ src,
                                 __nv_bfloat16* __restrict__ hi,
                                 __nv_bfloat16* __restrict__ lo) {
    int i = blockIdx.x * 256 + threadIdx.x;
    float x = src[i];
    __nv_bfloat16 h = __float2bfloat16(x);
    hi[i] = h;
    lo[i] = __float2bfloat16(x - __bfloat162float(h));
}

// h fp32 -> hi/lo bf16, 8 elems/thread
__global__ void convert_h_kernel(const float* __restrict__ src,
                                 __nv_bfloat16* __restrict__ hi,
                                 __nv_bfloat16* __restrict__ lo) {
    size_t i = ((size_t)blockIdx.x * 256 + threadIdx.x) * 8;
    float4 a = *(const float4*)(src + i);
    float4 b = *(const float4*)(src + i + 4);
    float x[8] = {a.x, a.y, a.z, a.w, b.x, b.y, b.z, b.w};
    uint32_t hw[4], lw[4];
    #pragma unroll
    for (int g = 0; g < 4; ++g) {
        __nv_bfloat16 h0 = __float2bfloat16(x[2*g]);
        __nv_bfloat16 h1 = __float2bfloat16(x[2*g+1]);
        __nv_bfloat16 l0 = __float2bfloat16(x[2*g]   - __bfloat162float(h0));
        __nv_bfloat16 l1 = __float2bfloat16(x[2*g+1] - __bfloat162float(h1));
        hw[g] = (uint32_t)__bfloat16_as_ushort(h0) | ((uint32_t)__bfloat16_as_ushort(h1) << 16);
        lw[g] = (uint32_t)__bfloat16_as_ushort(l0) | ((uint32_t)__bfloat16_as_ushort(l1) << 16);
    }
    *(uint4*)(hi + i) = make_uint4(hw[0], hw[1], hw[2], hw[3]);
    *(uint4*)(lo + i) = make_uint4(lw[0], lw[1], lw[2], lw[3]);
}

// Wc = Wf@Wo1 (pre-split hi/lo), bc = Wf@bo1+bf.  32 blocks x 8 rows.
__global__ void fold2_kernel(const float* __restrict__ Wf, const float* __restrict__ Wo1,
                             const float* __restrict__ bo1, const float* __restrict__ bfb,
                             __nv_bfloat16* __restrict__ Wch, __nv_bfloat16* __restrict__ Wcl,
                             float* __restrict__ bc) {
    __shared__ float sWf[8][256];
    const int t = threadIdx.x, o0 = blockIdx.x * 8;
    #pragma unroll
    for (int r = 0; r < 8; ++r) sWf[r][t] = Wf[(o0 + r) * 256 + t];
    __syncthreads();
    float acc[8] = {0,0,0,0,0,0,0,0};
    #pragma unroll 4
    for (int h = 0; h < 256; ++h) {
        float x = Wo1[h * 256 + t];
        #pragma unroll
        for (int r = 0; r < 8; ++r) acc[r] = fmaf(sWf[r][h], x, acc[r]);
    }
    #pragma unroll
    for (int r = 0; r < 8; ++r) {
        float v = acc[r];
        __nv_bfloat16 hh = __float2bfloat16(v);
        Wch[(o0 + r) * 256 + t] = hh;
        Wcl[(o0 + r) * 256 + t] = __float2bfloat16(v - __bfloat162float(hh));
    }
    if (t < 8) {
        float a = 0.f;
        for (int h = 0; h < 256; ++h) a = fmaf(sWf[t][h], bo1[h], a);
        bc[o0 + t] = a + bfb[o0 + t];
    }
}

// ---------------- pipelined mma.sync GEMM ------------------------------------
// C[M, 128 cols @ ncol0] = act(A @ W^T + bias). A,W pre-split bf16 hi/lo.
// Block 256 thr (8 warps: 2M x 4N), tile 128x128x32, 4-stage cp.async pipeline.
// Stage layout (bytes): Ah@0 Al@10240 Bh@20480 Bl@30720, row stride 80B.
// DUAL: NY=4, y<2 -> set0, else set1; ncol0=(y&1)*128.  else NY=2, y=col half.

#define STG_B   40960
#define SMEM_DYN (4 * STG_B + 1024)

template<bool GATHER, bool RELU, bool DUAL>
__global__ void __launch_bounds__(256)
gemm2(const __nv_bfloat16* __restrict__ Ah, const __nv_bfloat16* __restrict__ Al,
      const __nv_bfloat16* __restrict__ W0h, const __nv_bfloat16* __restrict__ W0l,
      const float* __restrict__ bias0, float* __restrict__ C0,
      const __nv_bfloat16* __restrict__ W1h, const __nv_bfloat16* __restrict__ W1l,
      const float* __restrict__ bias1, float* __restrict__ C1,
      int Mtiles) {
    extern __shared__ char smem[];
    const uint32_t sb = smem_u32(smem);
    float* sbias = (float*)(smem + 4 * STG_B);
    const int t = threadIdx.x, lane = t & 31, wid = t >> 5;

    constexpr int NY = DUAL ? 4 : 2;
    const int y  = blockIdx.x & (NY - 1);
    const int tb = blockIdx.x >> (DUAL ? 2 : 1);
    const int NTB = gridDim.x >> (DUAL ? 2 : 1);

    const __nv_bfloat16 *Wh, *Wl;
    const float* bias;
    float* C;
    if (DUAL && y >= 2) { Wh = W1h; Wl = W1l; bias = bias1; C = C1; }
    else                { Wh = W0h; Wl = W0l; bias = bias0; C = C0; }
    const int ncol0 = (y & 1) * 128;

    if (t < 128) sbias[t] = bias[ncol0 + t];

    // per-thread chunk decode (8 chunks/stage)
    // s = t + u*256 in [0,2048): isB = s>>10, arr(hi/lo) = (s>>9)&1,
    // row = (s>>2)&127, seg = s&3.
    int tiles = 0;
    for (int mt = tb; mt < Mtiles; mt += NTB) ++tiles;
    const int QS = tiles * 8;

    auto cp_stage = [&](int q) {
        const int lt = q >> 3, kt = q & 7;
        const int mt = tb + lt * NTB;
        const uint32_t db = sb + (uint32_t)(q & 3) * STG_B;
        #pragma unroll
        for (int u = 0; u < 8; ++u) {
            const int s = t + (u << 8);
            const int isB = s >> 10;
            const int arr = (s >> 9) & 1;
            const int row = (s >> 2) & 127;
            const int seg = s & 3;
            const uint32_t dst = db + (uint32_t)(isB * 20480 + arr * 10240
                               + row * 80 + seg * 16);
            const __nv_bfloat16* src;
            if (isB) {
                src = (arr ? Wl : Wh) + (ncol0 + row) * 256 + kt * 32 + seg * 8;
            } else {
                int g = mt * 128 + row;
                if (GATHER) g = (g >> 2) * 12 + 3 * (g & 3);
                src = (arr ? Al : Ah) + (size_t)g * 256 + kt * 32 + seg * 8;
            }
            cp16(dst, src);
        }
        asm volatile("cp.async.commit_group;\n" ::: "memory");
    };

    // fragment addressing (validated in R3, stride 40 bf16 = 80B)
    const int wm = (wid & 1) * 64;
    const int wn = (wid >> 1) * 32;
    const uint32_t aoff = (uint32_t)((wm + (lane & 15)) * 80 + ((lane >> 4) << 4));
    const uint32_t boff = (uint32_t)((lane & 7) * 80 + (((lane >> 3) & 1) << 4));

    float c[4][4][4];
    #pragma unroll
    for (int i = 0; i < 4; ++i)
        #pragma unroll
        for (int j = 0; j < 4; ++j)
            #pragma unroll
            for (int e = 0; e < 4; ++e) c[i][j][e] = 0.f;

    const int npre = QS < 3 ? QS : 3;
    for (int q = 0; q < npre; ++q) cp_stage(q);

    for (int q = 0; q < QS; ++q) {
        const int kt = q & 7;
        asm volatile("cp.async.wait_group 2;\n" ::: "memory");
        __syncthreads();
        if (q + 3 < QS) cp_stage(q + 3);

        // ---- compute stage q ------------------------------------------------
        {
            const uint32_t ab = sb + (uint32_t)(q & 3) * STG_B;
            const uint32_t albase = ab + 10240;
            const uint32_t bhbase = ab + 20480;
            const uint32_t blbase = ab + 30720;
            #pragma unroll
            for (int ks = 0; ks < 32; ks += 16) {
                uint32_t rbh[4][2], rbl[4][2];
                #pragma unroll
                for (int j = 0; j < 4; ++j) {
                    const uint32_t o = boff + (uint32_t)((wn + 8 * j) * 80 + ks * 2);
                    ldmatrix_x2(rbh[j][0], rbh[j][1], bhbase + o);
                    ldmatrix_x2(rbl[j][0], rbl[j][1], blbase + o);
                }
                #pragma unroll
                for (int i = 0; i < 4; ++i) {
                    const uint32_t o = aoff + (uint32_t)(i * 16 * 80 + ks * 2);
                    uint32_t ah0, ah1, ah2, ah3, al0, al1, al2, al3;
                    ldmatrix_x4(ah0, ah1, ah2, ah3, ab + o);
                    ldmatrix_x4(al0, al1, al2, al3, albase + o);
                    #pragma unroll
                    for (int j = 0; j < 4; ++j) {
                        mma_bf16(c[i][j], ah0, ah1, ah2, ah3, rbh[j][0], rbh[j][1]);
                        mma_bf16(c[i][j], ah0, ah1, ah2, ah3, rbl[j][0], rbl[j][1]);
                        mma_bf16(c[i][j], al0, al1, al2, al3, rbh[j][0], rbh[j][1]);
                    }
                }
            }
        }

        if (kt == 7) {
            // ---- epilogue for finished tile --------------------------------
            const int mt = tb + (q >> 3) * NTB;
            const int gr = lane >> 2, gc = (lane & 3) * 2;
            const int mbase = mt * 128 + wm;
            #pragma unroll
            for (int i = 0; i < 4; ++i) {
                #pragma unroll
                for (int j = 0; j < 4; ++j) {
                    const int col = wn + 8 * j + gc;
                    const float b0v = sbias[col], b1v = sbias[col + 1];
                    float v0 = c[i][j][0] + b0v, v1 = c[i][j][1] + b1v;
                    float v2 = c[i][j][2] + b0v, v3 = c[i][j][3] + b1v;
                    if (RELU) {
                        v0 = fmaxf(v0, 0.f); v1 = fmaxf(v1, 0.f);
                        v2 = fmaxf(v2, 0.f); v3 = fmaxf(v3, 0.f);
                    }
                    const int r0 = mbase + 16 * i + gr;
                    *(float2*)&C[(size_t)r0 * 256 + ncol0 + col]       = make_float2(v0, v1);
                    *(float2*)&C[(size_t)(r0 + 8) * 256 + ncol0 + col] = make_float2(v2, v3);
                    c[i][j][0] = 0.f; c[i][j][1] = 0.f;
                    c[i][j][2] = 0.f; c[i][j][3] = 0.f;
                }
            }
        }
    }
}

// ---------------- attention ---------------------------------------------------
// block = 128 thr = one batch; warp w -> sel row (node 3w). f1 written bf16 hi/lo.
__global__ void __launch_bounds__(128)
attn_kernel(const float* __restrict__ q1, const float* __restrict__ k1,
            const float* __restrict__ wh1, const float* __restrict__ label,
            const float* __restrict__ adj,
            __nv_bfloat16* __restrict__ f1h, __nv_bfloat16* __restrict__ f1l) {
    __shared__ float sk [NNODE * 256];
    __shared__ float swh[NNODE * 256];
    __shared__ float sq [4 * 256];
    __shared__ float sadj[4 * NNODE];
    __shared__ float slab[NNODE];

    const int b = blockIdx.x, t = threadIdx.x;

    const float4* k4 = (const float4*)(k1  + (size_t)b * NNODE * 256);
    const float4* w4 = (const float4*)(wh1 + (size_t)b * NNODE * 256);
    const float4* q4 = (const float4*)(q1  + (size_t)b * 4 * 256);
    float4* dk = (float4*)sk;
    float4* dw = (float4*)swh;
    float4* dq = (float4*)sq;
    #pragma unroll
    for (int u = 0; u < 6; ++u) { dk[t + 128 * u] = k4[t + 128 * u];
                                  dw[t + 128 * u] = w4[t + 128 * u]; }
    #pragma unroll
    for (int u = 0; u < 2; ++u)   dq[t + 128 * u] = q4[t + 128 * u];
    if (t < NNODE) slab[t] = label[b * NNODE + t];
    if (t < 4 * NNODE) {
        int i = t / NNODE, m = t % NNODE;
        sadj[t] = adj[(3 * i) * NNODE + m];
    }
    __syncthreads();

    const int w = t >> 5, l = t & 31;
    float qv[8];
    {
        const float4* qp = (const float4*)(sq + w * 256 + l * 8);
        float4 a = qp[0], bq_ = qp[1];
        qv[0]=a.x; qv[1]=a.y; qv[2]=a.z; qv[3]=a.w;
        qv[4]=bq_.x; qv[5]=bq_.y; qv[6]=bq_.z; qv[7]=bq_.w;
    }
    float s[NNODE];
    #pragma unroll
    for (int m = 0; m < NNODE; ++m) {
        const float4* kp = (const float4*)(sk + m * 256 + l * 8);
        float4 a = kp[0], bb = kp[1];
        s[m] = qv[0]*a.x + qv[1]*a.y + qv[2]*a.z + qv[3]*a.w
             + qv[4]*bb.x + qv[5]*bb.y + qv[6]*bb.z + qv[7]*bb.w;
    }
    #pragma unroll
    for (int m = 0; m < NNODE; ++m)
        #pragma unroll
        for (int off = 16; off > 0; off >>= 1)
            s[m] += __shfl_xor_sync(0xffffffffu, s[m], off);

    float mx = -3.0e38f;
    #pragma unroll
    for (int m = 0; m < NNODE; ++m) {
        float sm = (sadj[w * NNODE + m] > 0.5f) ? s[m] : -9.0e15f;
        s[m] = sm;
        mx = fmaxf(mx, sm);
    }
    float sum = 0.f;
    #pragma unroll
    for (int m = 0; m < NNODE; ++m) { float p = expf(s[m] - mx); s[m] = p; sum += p; }
    const float inv = 1.f / sum;
    #pragma unroll
    for (int m = 0; m < NNODE; ++m) s[m] = s[m] * inv * slab[m];

    float o[8] = {0,0,0,0,0,0,0,0};
    #pragma unroll
    for (int m = 0; m < NNODE; ++m) {
        const float4* wp = (const float4*)(swh + m * 256 + l * 8);
        float4 a = wp[0], bb = wp[1];
        float am = s[m];
        o[0] = fmaf(am, a.x, o[0]); o[1] = fmaf(am, a.y, o[1]);
        o[2] = fmaf(am, a.z, o[2]); o[3] = fmaf(am, a.w, o[3]);
        o[4] = fmaf(am, bb.x, o[4]); o[5] = fmaf(am, bb.y, o[5]);
        o[6] = fmaf(am, bb.z, o[6]); o[7] = fmaf(am, bb.w, o[7]);
    }
    uint32_t ph[4], pl[4];
    #pragma unroll
    for (int g = 0; g < 4; ++g) {
        __nv_bfloat16 h0 = __float2bfloat16(o[2*g]);
        __nv_bfloat16 h1 = __float2bfloat16(o[2*g+1]);
        __nv_bfloat16 l0 = __float2bfloat16(o[2*g]   - __bfloat162float(h0));
        __nv_bfloat16 l1 = __float2bfloat16(o[2*g+1] - __bfloat162float(h1));
        ph[g] = (uint32_t)__bfloat16_as_ushort(h0) | ((uint32_t)__bfloat16_as_ushort(h1) << 16);
        pl[g] = (uint32_t)__bfloat16_as_ushort(l0) | ((uint32_t)__bfloat16_as_ushort(l1) << 16);
    }
    const size_t idx = (size_t)(b * 4 + w) * 256 + l * 8;
    *(uint4*)(f1h + idx) = make_uint4(ph[0], ph[1], ph[2], ph[3]);
    *(uint4*)(f1l + idx) = make_uint4(pl[0], pl[1], pl[2], pl[3]);
}

// ---------------- host launch -------------------------------------------------
extern "C" void kernel_launch(void* const* d_in, const int* in_sizes, int n_in,
                              void* d_out, int out_size) {
    const float* h     = (const float*)d_in[0];
    const float* adj   = (const float*)d_in[1];
    const float* label = (const float*)d_in[2];
    const float* Wv    = (const float*)d_in[3];
    const float* bv    = (const float*)d_in[4];
    const float* Wk    = (const float*)d_in[5];
    const float* bk    = (const float*)d_in[6];
    const float* Wq    = (const float*)d_in[7];
    const float* bq    = (const float*)d_in[8];
    const float* Wo1   = (const float*)d_in[9];
    const float* bo1   = (const float*)d_in[10];
    const float* Wf    = (const float*)d_in[11];
    const float* bf    = (const float*)d_in[12];
    float* out = (float*)d_out;

    float *p_Wh1, *p_k1, *p_q1, *p_bc;
    __nv_bfloat16 *p_hh, *p_hl, *p_f1h, *p_f1l;
    __nv_bfloat16 *p_Wvh, *p_Wvl, *p_Wkh, *p_Wkl, *p_Wqh, *p_Wql, *p_Wch, *p_Wcl;
    cudaGetSymbolAddress((void**)&p_Wh1, g_Wh1);
    cudaGetSymbolAddress((void**)&p_k1,  g_k1);
    cudaGetSymbolAddress((void**)&p_q1,  g_q1);
    cudaGetSymbolAddress((void**)&p_bc,  g_bc);
    cudaGetSymbolAddress((void**)&p_hh,  g_hh);
    cudaGetSymbolAddress((void**)&p_hl,  g_hl);
    cudaGetSymbolAddress((void**)&p_f1h, g_f1h);
    cudaGetSymbolAddress((void**)&p_f1l, g_f1l);
    cudaGetSymbolAddress((void**)&p_Wvh, g_Wv_h);
    cudaGetSymbolAddress((void**)&p_Wvl, g_Wv_l);
    cudaGetSymbolAddress((void**)&p_Wkh, g_Wk_h);
    cudaGetSymbolAddress((void**)&p_Wkl, g_Wk_l);
    cudaGetSymbolAddress((void**)&p_Wqh, g_Wq_h);
    cudaGetSymbolAddress((void**)&p_Wql, g_Wq_l);
    cudaGetSymbolAddress((void**)&p_Wch, g_Wc_h);
    cudaGetSymbolAddress((void**)&p_Wcl, g_Wc_l);

    cudaFuncSetAttribute(gemm2<false, true, true>,
                         cudaFuncAttributeMaxDynamicSharedMemorySize, SMEM_DYN);
    cudaFuncSetAttribute(gemm2<true, true, false>,
                         cudaFuncAttributeMaxDynamicSharedMemorySize, SMEM_DYN);
    cudaFuncSetAttribute(gemm2<false, false, false>,
                         cudaFuncAttributeMaxDynamicSharedMemorySize, SMEM_DYN);

    convert_w_kernel<<<256, 256>>>(Wv, p_Wvh, p_Wvl);
    convert_w_kernel<<<256, 256>>>(Wk, p_Wkh, p_Wkl);
    convert_w_kernel<<<256, 256>>>(Wq, p_Wqh, p_Wql);
    fold2_kernel<<<32, 256>>>(Wf, Wo1, bo1, bf, p_Wch, p_Wcl, p_bc);
    convert_h_kernel<<<12288, 256>>>(h, p_hh, p_hl);

    // V+K GEMM: NY=4 (y<2 -> Wv/Wh1, y>=2 -> Wk/k1), 148 blocks, Mtiles=768
    gemm2<false, true, true><<<148, 256, SMEM_DYN>>>(
        p_hh, p_hl, p_Wvh, p_Wvl, bv, p_Wh1, p_Wkh, p_Wkl, bk, p_k1, M_VK / 128);

    // Q GEMM (gathered sel rows): NY=2, Mtiles=256
    gemm2<true, true, false><<<148, 256, SMEM_DYN>>>(
        p_hh, p_hl, p_Wqh, p_Wql, bq, p_q1,
        nullptr, nullptr, nullptr, nullptr, M_SEL / 128);

    attn_kernel<<<BATCH, 128>>>(p_q1, p_k1, p_Wh1, label, adj, p_f1h, p_f1l);

    // folded output GEMM straight into d_out: NY=2, Mtiles=256
    gemm2<false, false, false><<<148, 256, SMEM_DYN>>>(
        p_f1h, p_f1l, p_Wch, p_Wcl, p_bc, out,
        nullptr, nullptr, nullptr, nullptr, M_SEL / 128);
}

// round 6
// speedup vs baseline: 1.0457x; 1.0457x over previous
#include <cuda_runtime.h>
#include <cuda_bf16.h>
#include <cstdint>
#include <cstddef>

// ============================================================================
// GAT fusion, B=8192, N=12, D=256, SEL={0,3,6,9}.  sm_100 (no 'a' features):
// mma.sync.m16n8k16.bf16, bf16x3 split (hi*hi + hi*lo + lo*hi) fp32-grade,
// cp.async 4-stage pipeline, pass-reordered mma (16-deep independence).
// ============================================================================

#define BATCH   8192
#define NNODE   12
#define DIM     256
#define M_VK    (BATCH * NNODE)     // 98304
#define M_SEL   (BATCH * 4)         // 32768

// ---------------- scratch (device globals; no allocation) -------------------
__device__ __nv_bfloat16 g_hh[M_VK * DIM], g_hl[M_VK * DIM];   // h split
__device__ float g_Wh1[M_VK * DIM];
__device__ float g_k1 [M_VK * DIM];
__device__ float g_q1 [M_SEL * DIM];
__device__ __nv_bfloat16 g_f1h[M_SEL * DIM], g_f1l[M_SEL * DIM];
__device__ float g_bc [DIM];
__device__ float g_Wc_part[8 * DIM * DIM];
__device__ __nv_bfloat16 g_Wv_h[DIM*DIM], g_Wv_l[DIM*DIM];
__device__ __nv_bfloat16 g_Wk_h[DIM*DIM], g_Wk_l[DIM*DIM];
__device__ __nv_bfloat16 g_Wq_h[DIM*DIM], g_Wq_l[DIM*DIM];
__device__ __nv_bfloat16 g_Wc_h[DIM*DIM], g_Wc_l[DIM*DIM];

// ---------------- helpers ----------------------------------------------------
__device__ __forceinline__ uint32_t smem_u32(const void* p) {
    return (uint32_t)__cvta_generic_to_shared(p);
}
__device__ __forceinline__ void ldmatrix_x4(uint32_t& r0, uint32_t& r1,
                                            uint32_t& r2, uint32_t& r3, uint32_t addr) {
    asm volatile("ldmatrix.sync.aligned.m8n8.x4.shared.b16 {%0,%1,%2,%3}, [%4];\n"
                 : "=r"(r0), "=r"(r1), "=r"(r2), "=r"(r3) : "r"(addr));
}
__device__ __forceinline__ void ldmatrix_x2(uint32_t& r0, uint32_t& r1, uint32_t addr) {
    asm volatile("ldmatrix.sync.aligned.m8n8.x2.shared.b16 {%0,%1}, [%2];\n"
                 : "=r"(r0), "=r"(r1) : "r"(addr));
}
__device__ __forceinline__ void mma_bf16(float c[4],
                                         uint32_t a0, uint32_t a1, uint32_t a2, uint32_t a3,
                                         uint32_t b0, uint32_t b1) {
    asm volatile("mma.sync.aligned.m16n8k16.row.col.f32.bf16.bf16.f32 "
                 "{%0,%1,%2,%3}, {%4,%5,%6,%7}, {%8,%9}, {%0,%1,%2,%3};\n"
                 : "+f"(c[0]), "+f"(c[1]), "+f"(c[2]), "+f"(c[3])
                 : "r"(a0), "r"(a1), "r"(a2), "r"(a3), "r"(b0), "r"(b1));
}
__device__ __forceinline__ void cp16(uint32_t dst, const void* src) {
    asm volatile("cp.async.cg.shared.global [%0], [%1], 16;\n" :: "r"(dst), "l"(src));
}

// ---------------- prologue kernels -------------------------------------------
__global__ void convert_w_kernel(const float* __restrict__ src,
                                 __nv_bfloat16* __restrict__ hi,
                                 __nv_bfloat16* __restrict__ lo) {
    int i = blockIdx.x * 256 + threadIdx.x;
    float x = src[i];
    __nv_bfloat16 h = __float2bfloat16(x);
    hi[i] = h;
    lo[i] = __float2bfloat16(x - __bfloat162float(h));
}

// h fp32 -> hi/lo bf16, 8 elems/thread
__global__ void convert_h_kernel(const float* __restrict__ src,
                                 __nv_bfloat16* __restrict__ hi,
                                 __nv_bfloat16* __restrict__ lo) {
    size_t i = ((size_t)blockIdx.x * 256 + threadIdx.x) * 8;
    float4 a = *(const float4*)(src + i);
    float4 b = *(const float4*)(src + i + 4);
    float x[8] = {a.x, a.y, a.z, a.w, b.x, b.y, b.z, b.w};
    uint32_t hw[4], lw[4];
    #pragma unroll
    for (int g = 0; g < 4; ++g) {
        __nv_bfloat16 h0 = __float2bfloat16(x[2*g]);
        __nv_bfloat16 h1 = __float2bfloat16(x[2*g+1]);
        __nv_bfloat16 l0 = __float2bfloat16(x[2*g]   - __bfloat162float(h0));
        __nv_bfloat16 l1 = __float2bfloat16(x[2*g+1] - __bfloat162float(h1));
        hw[g] = (uint32_t)__bfloat16_as_ushort(h0) | ((uint32_t)__bfloat16_as_ushort(h1) << 16);
        lw[g] = (uint32_t)__bfloat16_as_ushort(l0) | ((uint32_t)__bfloat16_as_ushort(l1) << 16);
    }
    *(uint4*)(hi + i) = make_uint4(hw[0], hw[1], hw[2], hw[3]);
    *(uint4*)(lo + i) = make_uint4(lw[0], lw[1], lw[2], lw[3]);
}

// ---- fold, stage 1: partial Wc over k-slices.  grid (32, 8), block 256 ------
__global__ void fold_part_kernel(const float* __restrict__ Wf,
                                 const float* __restrict__ Wo1,
                                 float* __restrict__ part) {
    __shared__ float sWf[8][32];
    const int t = threadIdx.x, o0 = blockIdx.x * 8, kz = blockIdx.y * 32;
    {
        int r = t >> 5, hh = t & 31;
        sWf[r][hh] = Wf[(o0 + r) * 256 + kz + hh];
    }
    __syncthreads();
    float acc[8] = {0,0,0,0,0,0,0,0};
    #pragma unroll
    for (int hh = 0; hh < 32; ++hh) {
        float x = Wo1[(kz + hh) * 256 + t];
        #pragma unroll
        for (int r = 0; r < 8; ++r) acc[r] = fmaf(sWf[r][hh], x, acc[r]);
    }
    #pragma unroll
    for (int r = 0; r < 8; ++r)
        part[((size_t)blockIdx.y << 16) + (o0 + r) * 256 + t] = acc[r];
}

// ---- fold, stage 2: reduce partials, split to bf16 hi/lo, compute bc --------
__global__ void fold_reduce_kernel(const float* __restrict__ part,
                                   const float* __restrict__ Wf,
                                   const float* __restrict__ bo1,
                                   const float* __restrict__ bfb,
                                   __nv_bfloat16* __restrict__ Wch,
                                   __nv_bfloat16* __restrict__ Wcl,
                                   float* __restrict__ bc) {
    const int o = blockIdx.x, t = threadIdx.x;
    float v = 0.f;
    #pragma unroll
    for (int kz = 0; kz < 8; ++kz) v += part[((size_t)kz << 16) + o * 256 + t];
    __nv_bfloat16 hh = __float2bfloat16(v);
    Wch[o * 256 + t] = hh;
    Wcl[o * 256 + t] = __float2bfloat16(v - __bfloat162float(hh));

    __shared__ float red[256];
    red[t] = Wf[o * 256 + t] * bo1[t];
    __syncthreads();
    #pragma unroll
    for (int s = 128; s > 0; s >>= 1) {
        if (t < s) red[t] += red[t + s];
        __syncthreads();
    }
    if (t == 0) bc[o] = red[0] + bfb[o];
}

// ---------------- pipelined mma.sync GEMM ------------------------------------
// C[M, 128 cols @ ncol0] = act(A @ W^T + bias). A,W pre-split bf16 hi/lo.
// Block 256 thr (8 warps: 2M x 4N), tile 128x128x32, 4-stage cp.async pipeline.
// Stage layout (bytes): Ah@0 Al@10240 Bh@20480 Bl@30720, row stride 80B.
// mma passes reordered: hh, hl, lh loops OUTSIDE (i,j) -> 16-deep independence.

#define STG_B   40960
#define SMEM_DYN (4 * STG_B + 1024)

template<bool GATHER, bool RELU, bool DUAL>
__global__ void __launch_bounds__(256)
gemm2(const __nv_bfloat16* __restrict__ Ah, const __nv_bfloat16* __restrict__ Al,
      const __nv_bfloat16* __restrict__ W0h, const __nv_bfloat16* __restrict__ W0l,
      const float* __restrict__ bias0, float* __restrict__ C0,
      const __nv_bfloat16* __restrict__ W1h, const __nv_bfloat16* __restrict__ W1l,
      const float* __restrict__ bias1, float* __restrict__ C1,
      int Mtiles) {
    extern __shared__ char smem[];
    const uint32_t sb = smem_u32(smem);
    float* sbias = (float*)(smem + 4 * STG_B);
    const int t = threadIdx.x, lane = t & 31, wid = t >> 5;

    constexpr int NY = DUAL ? 4 : 2;
    const int y  = blockIdx.x & (NY - 1);
    const int tb = blockIdx.x >> (DUAL ? 2 : 1);
    const int NTB = gridDim.x >> (DUAL ? 2 : 1);

    const __nv_bfloat16 *Wh, *Wl;
    const float* bias;
    float* C;
    if (DUAL && y >= 2) { Wh = W1h; Wl = W1l; bias = bias1; C = C1; }
    else                { Wh = W0h; Wl = W0l; bias = bias0; C = C0; }
    const int ncol0 = (y & 1) * 128;

    if (t < 128) sbias[t] = bias[ncol0 + t];

    int tiles = 0;
    for (int mt = tb; mt < Mtiles; mt += NTB) ++tiles;
    const int QS = tiles * 8;

    auto cp_stage = [&](int q) {
        const int lt = q >> 3, kt = q & 7;
        const int mt = tb + lt * NTB;
        const uint32_t db = sb + (uint32_t)(q & 3) * STG_B;
        #pragma unroll
        for (int u = 0; u < 8; ++u) {
            const int s = t + (u << 8);
            const int isB = s >> 10;
            const int arr = (s >> 9) & 1;
            const int row = (s >> 2) & 127;
            const int seg = s & 3;
            const uint32_t dst = db + (uint32_t)(isB * 20480 + arr * 10240
                               + row * 80 + seg * 16);
            const __nv_bfloat16* src;
            if (isB) {
                src = (arr ? Wl : Wh) + (ncol0 + row) * 256 + kt * 32 + seg * 8;
            } else {
                int g = mt * 128 + row;
                if (GATHER) g = (g >> 2) * 12 + 3 * (g & 3);
                src = (arr ? Al : Ah) + (size_t)g * 256 + kt * 32 + seg * 8;
            }
            cp16(dst, src);
        }
        asm volatile("cp.async.commit_group;\n" ::: "memory");
    };

    const int wm = (wid & 1) * 64;
    const int wn = (wid >> 1) * 32;
    const uint32_t aoff = (uint32_t)((wm + (lane & 15)) * 80 + ((lane >> 4) << 4));
    const uint32_t boff = (uint32_t)((lane & 7) * 80 + (((lane >> 3) & 1) << 4));

    float c[4][4][4];
    #pragma unroll
    for (int i = 0; i < 4; ++i)
        #pragma unroll
        for (int j = 0; j < 4; ++j)
            #pragma unroll
            for (int e = 0; e < 4; ++e) c[i][j][e] = 0.f;

    const int npre = QS < 3 ? QS : 3;
    for (int q = 0; q < npre; ++q) cp_stage(q);

    for (int q = 0; q < QS; ++q) {
        const int kt = q & 7;
        asm volatile("cp.async.wait_group 2;\n" ::: "memory");
        __syncthreads();
        if (q + 3 < QS) cp_stage(q + 3);

        // ---- compute stage q: pass-reordered mma ---------------------------
        {
            const uint32_t ab = sb + (uint32_t)(q & 3) * STG_B;
            const uint32_t albase = ab + 10240;
            const uint32_t bhbase = ab + 20480;
            const uint32_t blbase = ab + 30720;
            #pragma unroll
            for (int ks = 0; ks < 32; ks += 16) {
                uint32_t rbh[4][2], rbl[4][2];
                uint32_t rah[4][4], ral[4][4];
                #pragma unroll
                for (int j = 0; j < 4; ++j) {
                    const uint32_t o = boff + (uint32_t)((wn + 8 * j) * 80 + ks * 2);
                    ldmatrix_x2(rbh[j][0], rbh[j][1], bhbase + o);
                    ldmatrix_x2(rbl[j][0], rbl[j][1], blbase + o);
                }
                #pragma unroll
                for (int i = 0; i < 4; ++i) {
                    const uint32_t o = aoff + (uint32_t)(i * 16 * 80 + ks * 2);
                    ldmatrix_x4(rah[i][0], rah[i][1], rah[i][2], rah[i][3], ab + o);
                    ldmatrix_x4(ral[i][0], ral[i][1], ral[i][2], ral[i][3], albase + o);
                }
                // pass 1: hi*hi  (16 independent mma)
                #pragma unroll
                for (int i = 0; i < 4; ++i)
                    #pragma unroll
                    for (int j = 0; j < 4; ++j)
                        mma_bf16(c[i][j], rah[i][0], rah[i][1], rah[i][2], rah[i][3],
                                 rbh[j][0], rbh[j][1]);
                // pass 2: hi*lo
                #pragma unroll
                for (int i = 0; i < 4; ++i)
                    #pragma unroll
                    for (int j = 0; j < 4; ++j)
                        mma_bf16(c[i][j], rah[i][0], rah[i][1], rah[i][2], rah[i][3],
                                 rbl[j][0], rbl[j][1]);
                // pass 3: lo*hi
                #pragma unroll
                for (int i = 0; i < 4; ++i)
                    #pragma unroll
                    for (int j = 0; j < 4; ++j)
                        mma_bf16(c[i][j], ral[i][0], ral[i][1], ral[i][2], ral[i][3],
                                 rbh[j][0], rbh[j][1]);
            }
        }

        if (kt == 7) {
            const int mt = tb + (q >> 3) * NTB;
            const int gr = lane >> 2, gc = (lane & 3) * 2;
            const int mbase = mt * 128 + wm;
            #pragma unroll
            for (int i = 0; i < 4; ++i) {
                #pragma unroll
                for (int j = 0; j < 4; ++j) {
                    const int col = wn + 8 * j + gc;
                    const float b0v = sbias[col], b1v = sbias[col + 1];
                    float v0 = c[i][j][0] + b0v, v1 = c[i][j][1] + b1v;
                    float v2 = c[i][j][2] + b0v, v3 = c[i][j][3] + b1v;
                    if (RELU) {
                        v0 = fmaxf(v0, 0.f); v1 = fmaxf(v1, 0.f);
                        v2 = fmaxf(v2, 0.f); v3 = fmaxf(v3, 0.f);
                    }
                    const int r0 = mbase + 16 * i + gr;
                    *(float2*)&C[(size_t)r0 * 256 + ncol0 + col]       = make_float2(v0, v1);
                    *(float2*)&C[(size_t)(r0 + 8) * 256 + ncol0 + col] = make_float2(v2, v3);
                    c[i][j][0] = 0.f; c[i][j][1] = 0.f;
                    c[i][j][2] = 0.f; c[i][j][3] = 0.f;
                }
            }
        }
    }
}

// ---------------- attention ---------------------------------------------------
__global__ void __launch_bounds__(128)
attn_kernel(const float* __restrict__ q1, const float* __restrict__ k1,
            const float* __restrict__ wh1, const float* __restrict__ label,
            const float* __restrict__ adj,
            __nv_bfloat16* __restrict__ f1h, __nv_bfloat16* __restrict__ f1l) {
    __shared__ float sk [NNODE * 256];
    __shared__ float swh[NNODE * 256];
    __shared__ float sq [4 * 256];
    __shared__ float sadj[4 * NNODE];
    __shared__ float slab[NNODE];

    const int b = blockIdx.x, t = threadIdx.x;

    const float4* k4 = (const float4*)(k1  + (size_t)b * NNODE * 256);
    const float4* w4 = (const float4*)(wh1 + (size_t)b * NNODE * 256);
    const float4* q4 = (const float4*)(q1  + (size_t)b * 4 * 256);
    float4* dk = (float4*)sk;
    float4* dw = (float4*)swh;
    float4* dq = (float4*)sq;
    #pragma unroll
    for (int u = 0; u < 6; ++u) { dk[t + 128 * u] = k4[t + 128 * u];
                                  dw[t + 128 * u] = w4[t + 128 * u]; }
    #pragma unroll
    for (int u = 0; u < 2; ++u)   dq[t + 128 * u] = q4[t + 128 * u];
    if (t < NNODE) slab[t] = label[b * NNODE + t];
    if (t < 4 * NNODE) {
        int i = t / NNODE, m = t % NNODE;
        sadj[t] = adj[(3 * i) * NNODE + m];
    }
    __syncthreads();

    const int w = t >> 5, l = t & 31;
    float qv[8];
    {
        const float4* qp = (const float4*)(sq + w * 256 + l * 8);
        float4 a = qp[0], bq_ = qp[1];
        qv[0]=a.x; qv[1]=a.y; qv[2]=a.z; qv[3]=a.w;
        qv[4]=bq_.x; qv[5]=bq_.y; qv[6]=bq_.z; qv[7]=bq_.w;
    }
    float s[NNODE];
    #pragma unroll
    for (int m = 0; m < NNODE; ++m) {
        const float4* kp = (const float4*)(sk + m * 256 + l * 8);
        float4 a = kp[0], bb = kp[1];
        s[m] = qv[0]*a.x + qv[1]*a.y + qv[2]*a.z + qv[3]*a.w
             + qv[4]*bb.x + qv[5]*bb.y + qv[6]*bb.z + qv[7]*bb.w;
    }
    #pragma unroll
    for (int m = 0; m < NNODE; ++m)
        #pragma unroll
        for (int off = 16; off > 0; off >>= 1)
            s[m] += __shfl_xor_sync(0xffffffffu, s[m], off);

    float mx = -3.0e38f;
    #pragma unroll
    for (int m = 0; m < NNODE; ++m) {
        float sm = (sadj[w * NNODE + m] > 0.5f) ? s[m] : -9.0e15f;
        s[m] = sm;
        mx = fmaxf(mx, sm);
    }
    float sum = 0.f;
    #pragma unroll
    for (int m = 0; m < NNODE; ++m) { float p = expf(s[m] - mx); s[m] = p; sum += p; }
    const float inv = 1.f / sum;
    #pragma unroll
    for (int m = 0; m < NNODE; ++m) s[m] = s[m] * inv * slab[m];

    float o[8] = {0,0,0,0,0,0,0,0};
    #pragma unroll
    for (int m = 0; m < NNODE; ++m) {
        const float4* wp = (const float4*)(swh + m * 256 + l * 8);
        float4 a = wp[0], bb = wp[1];
        float am = s[m];
        o[0] = fmaf(am, a.x, o[0]); o[1] = fmaf(am, a.y, o[1]);
        o[2] = fmaf(am, a.z, o[2]); o[3] = fmaf(am, a.w, o[3]);
        o[4] = fmaf(am, bb.x, o[4]); o[5] = fmaf(am, bb.y, o[5]);
        o[6] = fmaf(am, bb.z, o[6]); o[7] = fmaf(am, bb.w, o[7]);
    }
    uint32_t ph[4], pl[4];
    #pragma unroll
    for (int g = 0; g < 4; ++g) {
        __nv_bfloat16 h0 = __float2bfloat16(o[2*g]);
        __nv_bfloat16 h1 = __float2bfloat16(o[2*g+1]);
        __nv_bfloat16 l0 = __float2bfloat16(o[2*g]   - __bfloat162float(h0));
        __nv_bfloat16 l1 = __float2bfloat16(o[2*g+1] - __bfloat162float(h1));
        ph[g] = (uint32_t)__bfloat16_as_ushort(h0) | ((uint32_t)__bfloat16_as_ushort(h1) << 16);
        pl[g] = (uint32_t)__bfloat16_as_ushort(l0) | ((uint32_t)__bfloat16_as_ushort(l1) << 16);
    }
    const size_t idx = (size_t)(b * 4 + w) * 256 + l * 8;
    *(uint4*)(f1h + idx) = make_uint4(ph[0], ph[1], ph[2], ph[3]);
    *(uint4*)(f1l + idx) = make_uint4(pl[0], pl[1], pl[2], pl[3]);
}

// ---------------- host launch -------------------------------------------------
extern "C" void kernel_launch(void* const* d_in, const int* in_sizes, int n_in,
                              void* d_out, int out_size) {
    const float* h     = (const float*)d_in[0];
    const float* adj   = (const float*)d_in[1];
    const float* label = (const float*)d_in[2];
    const float* Wv    = (const float*)d_in[3];
    const float* bv    = (const float*)d_in[4];
    const float* Wk    = (const float*)d_in[5];
    const float* bk    = (const float*)d_in[6];
    const float* Wq    = (const float*)d_in[7];
    const float* bq    = (const float*)d_in[8];
    const float* Wo1   = (const float*)d_in[9];
    const float* bo1   = (const float*)d_in[10];
    const float* Wf    = (const float*)d_in[11];
    const float* bf    = (const float*)d_in[12];
    float* out = (float*)d_out;

    float *p_Wh1, *p_k1, *p_q1, *p_bc, *p_part;
    __nv_bfloat16 *p_hh, *p_hl, *p_f1h, *p_f1l;
    __nv_bfloat16 *p_Wvh, *p_Wvl, *p_Wkh, *p_Wkl, *p_Wqh, *p_Wql, *p_Wch, *p_Wcl;
    cudaGetSymbolAddress((void**)&p_Wh1, g_Wh1);
    cudaGetSymbolAddress((void**)&p_k1,  g_k1);
    cudaGetSymbolAddress((void**)&p_q1,  g_q1);
    cudaGetSymbolAddress((void**)&p_bc,  g_bc);
    cudaGetSymbolAddress((void**)&p_part, g_Wc_part);
    cudaGetSymbolAddress((void**)&p_hh,  g_hh);
    cudaGetSymbolAddress((void**)&p_hl,  g_hl);
    cudaGetSymbolAddress((void**)&p_f1h, g_f1h);
    cudaGetSymbolAddress((void**)&p_f1l, g_f1l);
    cudaGetSymbolAddress((void**)&p_Wvh, g_Wv_h);
    cudaGetSymbolAddress((void**)&p_Wvl, g_Wv_l);
    cudaGetSymbolAddress((void**)&p_Wkh, g_Wk_h);
    cudaGetSymbolAddress((void**)&p_Wkl, g_Wk_l);
    cudaGetSymbolAddress((void**)&p_Wqh, g_Wq_h);
    cudaGetSymbolAddress((void**)&p_Wql, g_Wq_l);
    cudaGetSymbolAddress((void**)&p_Wch, g_Wc_h);
    cudaGetSymbolAddress((void**)&p_Wcl, g_Wc_l);

    cudaFuncSetAttribute(gemm2<false, true, true>,
                         cudaFuncAttributeMaxDynamicSharedMemorySize, SMEM_DYN);
    cudaFuncSetAttribute(gemm2<true, true, false>,
                         cudaFuncAttributeMaxDynamicSharedMemorySize, SMEM_DYN);
    cudaFuncSetAttribute(gemm2<false, false, false>,
                         cudaFuncAttributeMaxDynamicSharedMemorySize, SMEM_DYN);

    convert_w_kernel<<<256, 256>>>(Wv, p_Wvh, p_Wvl);
    convert_w_kernel<<<256, 256>>>(Wk, p_Wkh, p_Wkl);
    convert_w_kernel<<<256, 256>>>(Wq, p_Wqh, p_Wql);
    fold_part_kernel<<<dim3(32, 8), 256>>>(Wf, Wo1, p_part);
    fold_reduce_kernel<<<256, 256>>>(p_part, Wf, bo1, bf, p_Wch, p_Wcl, p_bc);
    convert_h_kernel<<<12288, 256>>>(h, p_hh, p_hl);

    // V+K GEMM: NY=4 (y<2 -> Wv/Wh1, y>=2 -> Wk/k1), 148 blocks
    gemm2<false, true, true><<<148, 256, SMEM_DYN>>>(
        p_hh, p_hl, p_Wvh, p_Wvl, bv, p_Wh1, p_Wkh, p_Wkl, bk, p_k1, M_VK / 128);

    // Q GEMM (gathered sel rows): NY=2
    gemm2<true, true, false><<<148, 256, SMEM_DYN>>>(
        p_hh, p_hl, p_Wqh, p_Wql, bq, p_q1,
        nullptr, nullptr, nullptr, nullptr, M_SEL / 128);

    attn_kernel<<<BATCH, 128>>>(p_q1, p_k1, p_Wh1, label, adj, p_f1h, p_f1l);

    // folded output GEMM straight into d_out: NY=2
    gemm2<false, false, false><<<148, 256, SMEM_DYN>>>(
        p_f1h, p_f1l, p_Wch, p_Wcl, p_bc, out,
        nullptr, nullptr, nullptr, nullptr, M_SEL / 128);
}

// round 7
// speedup vs baseline: 1.2490x; 1.1944x over previous
#include <cuda_runtime.h>
#include <cuda_fp16.h>
#include <cstdint>
#include <cstddef>

// ============================================================================
// GAT fusion, B=8192, N=12, D=256, SEL={0,3,6,9}.  sm_100 legacy-mma edition.
// Key fact (measured R3/R5/R6): mma.sync throughput ~18cyc/SMSP -> time is
// proportional to mma count. So: fp16 splits; K,Q GEMMs fp16x3 (feed softmax,
// need ~2^-22); V,out GEMMs fp16x1 (linear-benign, ~3e-4 rel).
// ============================================================================

#define BATCH   8192
#define NNODE   12
#define DIM     256
#define M_VK    (BATCH * NNODE)     // 98304
#define M_SEL   (BATCH * 4)         // 32768

// ---------------- scratch (device globals; no allocation) -------------------
__device__ __half g_hh[M_VK * DIM], g_hl[M_VK * DIM];    // h split (fp16)
__device__ float g_Wh1[M_VK * DIM];
__device__ float g_k1 [M_VK * DIM];
__device__ float g_q1 [M_SEL * DIM];
__device__ __half g_f1h[M_SEL * DIM];
__device__ float g_bc [DIM];
__device__ float g_Wc_part[8 * DIM * DIM];
__device__ __half g_Wv_h[DIM*DIM], g_Wv_l[DIM*DIM];
__device__ __half g_Wk_h[DIM*DIM], g_Wk_l[DIM*DIM];
__device__ __half g_Wq_h[DIM*DIM], g_Wq_l[DIM*DIM];
__device__ __half g_Wc_h[DIM*DIM];

// ---------------- helpers ----------------------------------------------------
__device__ __forceinline__ uint32_t smem_u32(const void* p) {
    return (uint32_t)__cvta_generic_to_shared(p);
}
__device__ __forceinline__ void ldmatrix_x4(uint32_t& r0, uint32_t& r1,
                                            uint32_t& r2, uint32_t& r3, uint32_t addr) {
    asm volatile("ldmatrix.sync.aligned.m8n8.x4.shared.b16 {%0,%1,%2,%3}, [%4];\n"
                 : "=r"(r0), "=r"(r1), "=r"(r2), "=r"(r3) : "r"(addr));
}
__device__ __forceinline__ void ldmatrix_x2(uint32_t& r0, uint32_t& r1, uint32_t addr) {
    asm volatile("ldmatrix.sync.aligned.m8n8.x2.shared.b16 {%0,%1}, [%2];\n"
                 : "=r"(r0), "=r"(r1) : "r"(addr));
}
__device__ __forceinline__ void mma_f16(float c[4],
                                        uint32_t a0, uint32_t a1, uint32_t a2, uint32_t a3,
                                        uint32_t b0, uint32_t b1) {
    asm volatile("mma.sync.aligned.m16n8k16.row.col.f32.f16.f16.f32 "
                 "{%0,%1,%2,%3}, {%4,%5,%6,%7}, {%8,%9}, {%0,%1,%2,%3};\n"
                 : "+f"(c[0]), "+f"(c[1]), "+f"(c[2]), "+f"(c[3])
                 : "r"(a0), "r"(a1), "r"(a2), "r"(a3), "r"(b0), "r"(b1));
}
__device__ __forceinline__ void cp16(uint32_t dst, const void* src) {
    asm volatile("cp.async.cg.shared.global [%0], [%1], 16;\n" :: "r"(dst), "l"(src));
}

// ---------------- prologue kernels -------------------------------------------
__global__ void convert_w_kernel(const float* __restrict__ src,
                                 __half* __restrict__ hi,
                                 __half* __restrict__ lo) {
    int i = blockIdx.x * 256 + threadIdx.x;
    float x = src[i];
    __half h = __float2half_rn(x);
    hi[i] = h;
    lo[i] = __float2half_rn(x - __half2float(h));
}

// h fp32 -> hi/lo fp16, 8 elems/thread
__global__ void convert_h_kernel(const float* __restrict__ src,
                                 __half* __restrict__ hi,
                                 __half* __restrict__ lo) {
    size_t i = ((size_t)blockIdx.x * 256 + threadIdx.x) * 8;
    float4 a = *(const float4*)(src + i);
    float4 b = *(const float4*)(src + i + 4);
    float x[8] = {a.x, a.y, a.z, a.w, b.x, b.y, b.z, b.w};
    uint32_t hw[4], lw[4];
    #pragma unroll
    for (int g = 0; g < 4; ++g) {
        __half h0 = __float2half_rn(x[2*g]);
        __half h1 = __float2half_rn(x[2*g+1]);
        __half l0 = __float2half_rn(x[2*g]   - __half2float(h0));
        __half l1 = __float2half_rn(x[2*g+1] - __half2float(h1));
        hw[g] = (uint32_t)__half_as_ushort(h0) | ((uint32_t)__half_as_ushort(h1) << 16);
        lw[g] = (uint32_t)__half_as_ushort(l0) | ((uint32_t)__half_as_ushort(l1) << 16);
    }
    *(uint4*)(hi + i) = make_uint4(hw[0], hw[1], hw[2], hw[3]);
    *(uint4*)(lo + i) = make_uint4(lw[0], lw[1], lw[2], lw[3]);
}

// ---- fold, stage 1: partial Wc over k-slices.  grid (32, 8), block 256 ------
__global__ void fold_part_kernel(const float* __restrict__ Wf,
                                 const float* __restrict__ Wo1,
                                 float* __restrict__ part) {
    __shared__ float sWf[8][32];
    const int t = threadIdx.x, o0 = blockIdx.x * 8, kz = blockIdx.y * 32;
    {
        int r = t >> 5, hh = t & 31;
        sWf[r][hh] = Wf[(o0 + r) * 256 + kz + hh];
    }
    __syncthreads();
    float acc[8] = {0,0,0,0,0,0,0,0};
    #pragma unroll
    for (int hh = 0; hh < 32; ++hh) {
        float x = Wo1[(kz + hh) * 256 + t];
        #pragma unroll
        for (int r = 0; r < 8; ++r) acc[r] = fmaf(sWf[r][hh], x, acc[r]);
    }
    #pragma unroll
    for (int r = 0; r < 8; ++r)
        part[((size_t)blockIdx.y << 16) + (o0 + r) * 256 + t] = acc[r];
}

// ---- fold, stage 2: reduce partials, fp16 hi, compute bc --------------------
__global__ void fold_reduce_kernel(const float* __restrict__ part,
                                   const float* __restrict__ Wf,
                                   const float* __restrict__ bo1,
                                   const float* __restrict__ bfb,
                                   __half* __restrict__ Wch,
                                   float* __restrict__ bc) {
    const int o = blockIdx.x, t = threadIdx.x;
    float v = 0.f;
    #pragma unroll
    for (int kz = 0; kz < 8; ++kz) v += part[((size_t)kz << 16) + o * 256 + t];
    Wch[o * 256 + t] = __float2half_rn(v);

    __shared__ float red[256];
    red[t] = Wf[o * 256 + t] * bo1[t];
    __syncthreads();
    #pragma unroll
    for (int s = 128; s > 0; s >>= 1) {
        if (t < s) red[t] += red[t + s];
        __syncthreads();
    }
    if (t == 0) bc[o] = red[0] + bfb[o];
}

// ---------------- pipelined mma.sync GEMM ------------------------------------
// C[M, 128 cols @ ncol0] = act(A @ W^T + bias). fp16 operands, fp32 accum.
// PASSES=3: arrays {Ah,Al,Bh,Bl}, mma passes hh+hl+lh (2^-22 accurate).
// PASSES=1: arrays {Ah,Bh}, single pass (fp16-grade, ~3e-4).
// Block 256 thr (8 warps: 2M x 4N), tile 128x128x32, 4-stage cp.async pipeline.
// Row stride 80B (64B payload + 16B pad) -> ldmatrix conflict-free.
// y = blockIdx.x & 1 selects the 128-col half; tb strides over M tiles.

template<int PASSES, bool GATHER, bool RELU>
__global__ void __launch_bounds__(256)
gemm2(const __half* __restrict__ Ah, const __half* __restrict__ Al,
      const __half* __restrict__ Wh, const __half* __restrict__ Wl,
      const float* __restrict__ bias, float* __restrict__ C,
      int Mtiles) {
    constexpr int ARR   = (PASSES == 3) ? 4 : 2;   // smem arrays per stage
    constexpr int NA    = (PASSES == 3) ? 2 : 1;   // A arrays
    constexpr uint32_t STG = ARR * 10240;

    extern __shared__ char smem[];
    const uint32_t sb = smem_u32(smem);
    float* sbias = (float*)(smem + 4 * STG);
    const int t = threadIdx.x, lane = t & 31, wid = t >> 5;

    const int y   = blockIdx.x & 1;
    const int tb  = blockIdx.x >> 1;
    const int NTB = gridDim.x >> 1;
    const int ncol0 = y * 128;

    if (t < 128) sbias[t] = bias[ncol0 + t];

    int tiles = 0;
    for (int mt = tb; mt < Mtiles; mt += NTB) ++tiles;
    const int QS = tiles * 8;

    auto cp_stage = [&](int q) {
        const int lt = q >> 3, kt = q & 7;
        const int mt = tb + lt * NTB;
        const uint32_t db = sb + (uint32_t)(q & 3) * STG;
        #pragma unroll
        for (int u = 0; u < ARR * 2; ++u) {
            const int s = t + (u << 8);
            const int id  = s >> 9;           // array index 0..ARR-1
            const int row = (s >> 2) & 127;
            const int seg = s & 3;
            const uint32_t dst = db + (uint32_t)(id * 10240 + row * 80 + seg * 16);
            const __half* src;
            if (id < NA) {                    // A arrays (0=hi, 1=lo)
                int g = mt * 128 + row;
                if (GATHER) g = (g >> 2) * 12 + 3 * (g & 3);
                src = (id ? Al : Ah) + (size_t)g * 256 + kt * 32 + seg * 8;
            } else {                          // B arrays (0=hi, 1=lo)
                src = ((id - NA) ? Wl : Wh) + (ncol0 + row) * 256 + kt * 32 + seg * 8;
            }
            cp16(dst, src);
        }
        asm volatile("cp.async.commit_group;\n" ::: "memory");
    };

    const int wm = (wid & 1) * 64;
    const int wn = (wid >> 1) * 32;
    const uint32_t aoff = (uint32_t)((wm + (lane & 15)) * 80 + ((lane >> 4) << 4));
    const uint32_t boff = (uint32_t)((lane & 7) * 80 + (((lane >> 3) & 1) << 4));

    float c[4][4][4];
    #pragma unroll
    for (int i = 0; i < 4; ++i)
        #pragma unroll
        for (int j = 0; j < 4; ++j)
            #pragma unroll
            for (int e = 0; e < 4; ++e) c[i][j][e] = 0.f;

    const int npre = QS < 3 ? QS : 3;
    for (int q = 0; q < npre; ++q) cp_stage(q);

    for (int q = 0; q < QS; ++q) {
        const int kt = q & 7;
        asm volatile("cp.async.wait_group 2;\n" ::: "memory");
        __syncthreads();
        if (q + 3 < QS) cp_stage(q + 3);

        {
            const uint32_t ab     = sb + (uint32_t)(q & 3) * STG;
            const uint32_t albase = ab + 10240;             // valid if PASSES==3
            const uint32_t bhbase = ab + NA * 10240;
            const uint32_t blbase = bhbase + 10240;         // valid if PASSES==3
            #pragma unroll
            for (int ks = 0; ks < 32; ks += 16) {
                uint32_t rbh[4][2], rah[4][4];
                #pragma unroll
                for (int j = 0; j < 4; ++j) {
                    const uint32_t o = boff + (uint32_t)((wn + 8 * j) * 80 + ks * 2);
                    ldmatrix_x2(rbh[j][0], rbh[j][1], bhbase + o);
                }
                #pragma unroll
                for (int i = 0; i < 4; ++i) {
                    const uint32_t o = aoff + (uint32_t)(i * 16 * 80 + ks * 2);
                    ldmatrix_x4(rah[i][0], rah[i][1], rah[i][2], rah[i][3], ab + o);
                }
                // pass 1: hi*hi
                #pragma unroll
                for (int i = 0; i < 4; ++i)
                    #pragma unroll
                    for (int j = 0; j < 4; ++j)
                        mma_f16(c[i][j], rah[i][0], rah[i][1], rah[i][2], rah[i][3],
                                rbh[j][0], rbh[j][1]);
                if constexpr (PASSES == 3) {
                    uint32_t rbl[4][2], ral[4][4];
                    #pragma unroll
                    for (int j = 0; j < 4; ++j) {
                        const uint32_t o = boff + (uint32_t)((wn + 8 * j) * 80 + ks * 2);
                        ldmatrix_x2(rbl[j][0], rbl[j][1], blbase + o);
                    }
                    #pragma unroll
                    for (int i = 0; i < 4; ++i) {
                        const uint32_t o = aoff + (uint32_t)(i * 16 * 80 + ks * 2);
                        ldmatrix_x4(ral[i][0], ral[i][1], ral[i][2], ral[i][3], albase + o);
                    }
                    // pass 2: hi*lo
                    #pragma unroll
                    for (int i = 0; i < 4; ++i)
                        #pragma unroll
                        for (int j = 0; j < 4; ++j)
                            mma_f16(c[i][j], rah[i][0], rah[i][1], rah[i][2], rah[i][3],
                                    rbl[j][0], rbl[j][1]);
                    // pass 3: lo*hi
                    #pragma unroll
                    for (int i = 0; i < 4; ++i)
                        #pragma unroll
                        for (int j = 0; j < 4; ++j)
                            mma_f16(c[i][j], ral[i][0], ral[i][1], ral[i][2], ral[i][3],
                                    rbh[j][0], rbh[j][1]);
                }
            }
        }

        if (kt == 7) {
            const int mt = tb + (q >> 3) * NTB;
            const int gr = lane >> 2, gc = (lane & 3) * 2;
            const int mbase = mt * 128 + wm;
            #pragma unroll
            for (int i = 0; i < 4; ++i) {
                #pragma unroll
                for (int j = 0; j < 4; ++j) {
                    const int col = wn + 8 * j + gc;
                    const float b0v = sbias[col], b1v = sbias[col + 1];
                    float v0 = c[i][j][0] + b0v, v1 = c[i][j][1] + b1v;
                    float v2 = c[i][j][2] + b0v, v3 = c[i][j][3] + b1v;
                    if (RELU) {
                        v0 = fmaxf(v0, 0.f); v1 = fmaxf(v1, 0.f);
                        v2 = fmaxf(v2, 0.f); v3 = fmaxf(v3, 0.f);
                    }
                    const int r0 = mbase + 16 * i + gr;
                    *(float2*)&C[(size_t)r0 * 256 + ncol0 + col]       = make_float2(v0, v1);
                    *(float2*)&C[(size_t)(r0 + 8) * 256 + ncol0 + col] = make_float2(v2, v3);
                    c[i][j][0] = 0.f; c[i][j][1] = 0.f;
                    c[i][j][2] = 0.f; c[i][j][3] = 0.f;
                }
            }
        }
    }
}

// ---------------- attention ---------------------------------------------------
// block = 128 thr = one batch; warp w -> sel row (node 3w). f1 written fp16.
__global__ void __launch_bounds__(128)
attn_kernel(const float* __restrict__ q1, const float* __restrict__ k1,
            const float* __restrict__ wh1, const float* __restrict__ label,
            const float* __restrict__ adj, __half* __restrict__ f1h) {
    __shared__ float sk [NNODE * 256];
    __shared__ float swh[NNODE * 256];
    __shared__ float sq [4 * 256];
    __shared__ float sadj[4 * NNODE];
    __shared__ float slab[NNODE];

    const int b = blockIdx.x, t = threadIdx.x;

    const float4* k4 = (const float4*)(k1  + (size_t)b * NNODE * 256);
    const float4* w4 = (const float4*)(wh1 + (size_t)b * NNODE * 256);
    const float4* q4 = (const float4*)(q1  + (size_t)b * 4 * 256);
    float4* dk = (float4*)sk;
    float4* dw = (float4*)swh;
    float4* dq = (float4*)sq;
    #pragma unroll
    for (int u = 0; u < 6; ++u) { dk[t + 128 * u] = k4[t + 128 * u];
                                  dw[t + 128 * u] = w4[t + 128 * u]; }
    #pragma unroll
    for (int u = 0; u < 2; ++u)   dq[t + 128 * u] = q4[t + 128 * u];
    if (t < NNODE) slab[t] = label[b * NNODE + t];
    if (t < 4 * NNODE) {
        int i = t / NNODE, m = t % NNODE;
        sadj[t] = adj[(3 * i) * NNODE + m];
    }
    __syncthreads();

    const int w = t >> 5, l = t & 31;
    float qv[8];
    {
        const float4* qp = (const float4*)(sq + w * 256 + l * 8);
        float4 a = qp[0], bq_ = qp[1];
        qv[0]=a.x; qv[1]=a.y; qv[2]=a.z; qv[3]=a.w;
        qv[4]=bq_.x; qv[5]=bq_.y; qv[6]=bq_.z; qv[7]=bq_.w;
    }
    float s[NNODE];
    #pragma unroll
    for (int m = 0; m < NNODE; ++m) {
        const float4* kp = (const float4*)(sk + m * 256 + l * 8);
        float4 a = kp[0], bb = kp[1];
        s[m] = qv[0]*a.x + qv[1]*a.y + qv[2]*a.z + qv[3]*a.w
             + qv[4]*bb.x + qv[5]*bb.y + qv[6]*bb.z + qv[7]*bb.w;
    }
    #pragma unroll
    for (int m = 0; m < NNODE; ++m)
        #pragma unroll
        for (int off = 16; off > 0; off >>= 1)
            s[m] += __shfl_xor_sync(0xffffffffu, s[m], off);

    float mx = -3.0e38f;
    #pragma unroll
    for (int m = 0; m < NNODE; ++m) {
        float sm = (sadj[w * NNODE + m] > 0.5f) ? s[m] : -9.0e15f;
        s[m] = sm;
        mx = fmaxf(mx, sm);
    }
    float sum = 0.f;
    #pragma unroll
    for (int m = 0; m < NNODE; ++m) { float p = expf(s[m] - mx); s[m] = p; sum += p; }
    const float inv = 1.f / sum;
    #pragma unroll
    for (int m = 0; m < NNODE; ++m) s[m] = s[m] * inv * slab[m];

    float o[8] = {0,0,0,0,0,0,0,0};
    #pragma unroll
    for (int m = 0; m < NNODE; ++m) {
        const float4* wp = (const float4*)(swh + m * 256 + l * 8);
        float4 a = wp[0], bb = wp[1];
        float am = s[m];
        o[0] = fmaf(am, a.x, o[0]); o[1] = fmaf(am, a.y, o[1]);
        o[2] = fmaf(am, a.z, o[2]); o[3] = fmaf(am, a.w, o[3]);
        o[4] = fmaf(am, bb.x, o[4]); o[5] = fmaf(am, bb.y, o[5]);
        o[6] = fmaf(am, bb.z, o[6]); o[7] = fmaf(am, bb.w, o[7]);
    }
    uint32_t pk[4];
    #pragma unroll
    for (int g = 0; g < 4; ++g) {
        __half2 h2 = __floats2half2_rn(o[2*g], o[2*g+1]);
        pk[g] = *(uint32_t*)&h2;
    }
    const size_t idx = (size_t)(b * 4 + w) * 256 + l * 8;
    *(uint4*)(f1h + idx) = make_uint4(pk[0], pk[1], pk[2], pk[3]);
}

// ---------------- host launch -------------------------------------------------
extern "C" void kernel_launch(void* const* d_in, const int* in_sizes, int n_in,
                              void* d_out, int out_size) {
    const float* h     = (const float*)d_in[0];
    const float* adj   = (const float*)d_in[1];
    const float* label = (const float*)d_in[2];
    const float* Wv    = (const float*)d_in[3];
    const float* bv    = (const float*)d_in[4];
    const float* Wk    = (const float*)d_in[5];
    const float* bk    = (const float*)d_in[6];
    const float* Wq    = (const float*)d_in[7];
    const float* bq    = (const float*)d_in[8];
    const float* Wo1   = (const float*)d_in[9];
    const float* bo1   = (const float*)d_in[10];
    const float* Wf    = (const float*)d_in[11];
    const float* bf    = (const float*)d_in[12];
    float* out = (float*)d_out;

    float *p_Wh1, *p_k1, *p_q1, *p_bc, *p_part;
    __half *p_hh, *p_hl, *p_f1h;
    __half *p_Wvh, *p_Wvl, *p_Wkh, *p_Wkl, *p_Wqh, *p_Wql, *p_Wch;
    cudaGetSymbolAddress((void**)&p_Wh1, g_Wh1);
    cudaGetSymbolAddress((void**)&p_k1,  g_k1);
    cudaGetSymbolAddress((void**)&p_q1,  g_q1);
    cudaGetSymbolAddress((void**)&p_bc,  g_bc);
    cudaGetSymbolAddress((void**)&p_part, g_Wc_part);
    cudaGetSymbolAddress((void**)&p_hh,  g_hh);
    cudaGetSymbolAddress((void**)&p_hl,  g_hl);
    cudaGetSymbolAddress((void**)&p_f1h, g_f1h);
    cudaGetSymbolAddress((void**)&p_Wvh, g_Wv_h);
    cudaGetSymbolAddress((void**)&p_Wvl, g_Wv_l);
    cudaGetSymbolAddress((void**)&p_Wkh, g_Wk_h);
    cudaGetSymbolAddress((void**)&p_Wkl, g_Wk_l);
    cudaGetSymbolAddress((void**)&p_Wqh, g_Wq_h);
    cudaGetSymbolAddress((void**)&p_Wql, g_Wq_l);
    cudaGetSymbolAddress((void**)&p_Wch, g_Wc_h);

    const int SMEM3 = 4 * 40960 + 1024;
    const int SMEM1 = 4 * 20480 + 1024;
    cudaFuncSetAttribute(gemm2<3, false, true>,
                         cudaFuncAttributeMaxDynamicSharedMemorySize, SMEM3);
    cudaFuncSetAttribute(gemm2<3, true, true>,
                         cudaFuncAttributeMaxDynamicSharedMemorySize, SMEM3);
    cudaFuncSetAttribute(gemm2<1, false, true>,
                         cudaFuncAttributeMaxDynamicSharedMemorySize, SMEM1);
    cudaFuncSetAttribute(gemm2<1, false, false>,
                         cudaFuncAttributeMaxDynamicSharedMemorySize, SMEM1);

    // Launch order puts the big K-GEMM at index 4 (the launch ncu captures).
    convert_h_kernel<<<12288, 256>>>(h, p_hh, p_hl);             // 1
    convert_w_kernel<<<256, 256>>>(Wv, p_Wvh, p_Wvl);            // 2
    convert_w_kernel<<<256, 256>>>(Wk, p_Wkh, p_Wkl);            // 3
    // K GEMM (fp16x3): k1 = relu(h@Wk^T + bk)                   // 4
    gemm2<3, false, true><<<148, 256, SMEM3>>>(
        p_hh, p_hl, p_Wkh, p_Wkl, bk, p_k1, M_VK / 128);
    // V GEMM (fp16x1): Wh1 = relu(h@Wv^T + bv)                  // 5
    gemm2<1, false, true><<<148, 256, SMEM1>>>(
        p_hh, nullptr, p_Wvh, nullptr, bv, p_Wh1, M_VK / 128);
    convert_w_kernel<<<256, 256>>>(Wq, p_Wqh, p_Wql);            // 6
    // Q GEMM (fp16x3, gathered): q1 = relu(h_sel@Wq^T + bq)     // 7
    gemm2<3, true, true><<<148, 256, SMEM3>>>(
        p_hh, p_hl, p_Wqh, p_Wql, bq, p_q1, M_SEL / 128);
    fold_part_kernel<<<dim3(32, 8), 256>>>(Wf, Wo1, p_part);     // 8
    fold_reduce_kernel<<<256, 256>>>(p_part, Wf, bo1, bf, p_Wch, p_bc);  // 9
    attn_kernel<<<BATCH, 128>>>(p_q1, p_k1, p_Wh1, label, adj, p_f1h);   // 10
    // out GEMM (fp16x1) straight into d_out                     // 11
    gemm2<1, false, false><<<148, 256, SMEM1>>>(
        p_f1h, nullptr, p_Wch, nullptr, p_bc, out, M_SEL / 128);
}

// round 8
// speedup vs baseline: 1.3813x; 1.1059x over previous
#include <cuda_runtime.h>
#include <cuda_fp16.h>
#include <cstdint>
#include <cstddef>

// ============================================================================
// GAT fusion, B=8192, N=12, D=256, SEL={0,3,6,9}.  sm_100 legacy-mma edition.
// R7 evidence: tensor=46%, occ=12.5% (1 CTA/SM, smem-capped). This round:
// 2-stage pipeline (82KB smem) -> 2 CTAs/SM -> overlap barriers with mma.
// K,Q GEMMs fp16x3 (softmax-accurate); V,out GEMMs fp16x1 (~3e-4 rel).
// ============================================================================

#define BATCH   8192
#define NNODE   12
#define DIM     256
#define M_VK    (BATCH * NNODE)     // 98304
#define M_SEL   (BATCH * 4)         // 32768

// ---------------- scratch (device globals; no allocation) -------------------
__device__ __half g_hh[M_VK * DIM], g_hl[M_VK * DIM];    // h split (fp16)
__device__ float g_Wh1[M_VK * DIM];
__device__ float g_k1 [M_VK * DIM];
__device__ float g_q1 [M_SEL * DIM];
__device__ __half g_f1h[M_SEL * DIM];
__device__ float g_bc [DIM];
__device__ float g_Wc_part[8 * DIM * DIM];
__device__ __half g_Wv_h[DIM*DIM], g_Wv_l[DIM*DIM];
__device__ __half g_Wk_h[DIM*DIM], g_Wk_l[DIM*DIM];
__device__ __half g_Wq_h[DIM*DIM], g_Wq_l[DIM*DIM];
__device__ __half g_Wc_h[DIM*DIM];

// ---------------- helpers ----------------------------------------------------
__device__ __forceinline__ uint32_t smem_u32(const void* p) {
    return (uint32_t)__cvta_generic_to_shared(p);
}
__device__ __forceinline__ void ldmatrix_x4(uint32_t& r0, uint32_t& r1,
                                            uint32_t& r2, uint32_t& r3, uint32_t addr) {
    asm volatile("ldmatrix.sync.aligned.m8n8.x4.shared.b16 {%0,%1,%2,%3}, [%4];\n"
                 : "=r"(r0), "=r"(r1), "=r"(r2), "=r"(r3) : "r"(addr));
}
__device__ __forceinline__ void ldmatrix_x2(uint32_t& r0, uint32_t& r1, uint32_t addr) {
    asm volatile("ldmatrix.sync.aligned.m8n8.x2.shared.b16 {%0,%1}, [%2];\n"
                 : "=r"(r0), "=r"(r1) : "r"(addr));
}
__device__ __forceinline__ void mma_f16(float c[4],
                                        uint32_t a0, uint32_t a1, uint32_t a2, uint32_t a3,
                                        uint32_t b0, uint32_t b1) {
    asm volatile("mma.sync.aligned.m16n8k16.row.col.f32.f16.f16.f32 "
                 "{%0,%1,%2,%3}, {%4,%5,%6,%7}, {%8,%9}, {%0,%1,%2,%3};\n"
                 : "+f"(c[0]), "+f"(c[1]), "+f"(c[2]), "+f"(c[3])
                 : "r"(a0), "r"(a1), "r"(a2), "r"(a3), "r"(b0), "r"(b1));
}
__device__ __forceinline__ void cp16(uint32_t dst, const void* src) {
    asm volatile("cp.async.cg.shared.global [%0], [%1], 16;\n" :: "r"(dst), "l"(src));
}

// ---------------- prologue kernels -------------------------------------------
__global__ void convert_w_kernel(const float* __restrict__ src,
                                 __half* __restrict__ hi,
                                 __half* __restrict__ lo) {
    int i = blockIdx.x * 256 + threadIdx.x;
    float x = src[i];
    __half h = __float2half_rn(x);
    hi[i] = h;
    lo[i] = __float2half_rn(x - __half2float(h));
}

// h fp32 -> hi/lo fp16, 8 elems/thread
__global__ void convert_h_kernel(const float* __restrict__ src,
                                 __half* __restrict__ hi,
                                 __half* __restrict__ lo) {
    size_t i = ((size_t)blockIdx.x * 256 + threadIdx.x) * 8;
    float4 a = *(const float4*)(src + i);
    float4 b = *(const float4*)(src + i + 4);
    float x[8] = {a.x, a.y, a.z, a.w, b.x, b.y, b.z, b.w};
    uint32_t hw[4], lw[4];
    #pragma unroll
    for (int g = 0; g < 4; ++g) {
        __half h0 = __float2half_rn(x[2*g]);
        __half h1 = __float2half_rn(x[2*g+1]);
        __half l0 = __float2half_rn(x[2*g]   - __half2float(h0));
        __half l1 = __float2half_rn(x[2*g+1] - __half2float(h1));
        hw[g] = (uint32_t)__half_as_ushort(h0) | ((uint32_t)__half_as_ushort(h1) << 16);
        lw[g] = (uint32_t)__half_as_ushort(l0) | ((uint32_t)__half_as_ushort(l1) << 16);
    }
    *(uint4*)(hi + i) = make_uint4(hw[0], hw[1], hw[2], hw[3]);
    *(uint4*)(lo + i) = make_uint4(lw[0], lw[1], lw[2], lw[3]);
}

// ---- fold, stage 1: partial Wc over k-slices.  grid (32, 8), block 256 ------
__global__ void fold_part_kernel(const float* __restrict__ Wf,
                                 const float* __restrict__ Wo1,
                                 float* __restrict__ part) {
    __shared__ float sWf[8][32];
    const int t = threadIdx.x, o0 = blockIdx.x * 8, kz = blockIdx.y * 32;
    {
        int r = t >> 5, hh = t & 31;
        sWf[r][hh] = Wf[(o0 + r) * 256 + kz + hh];
    }
    __syncthreads();
    float acc[8] = {0,0,0,0,0,0,0,0};
    #pragma unroll
    for (int hh = 0; hh < 32; ++hh) {
        float x = Wo1[(kz + hh) * 256 + t];
        #pragma unroll
        for (int r = 0; r < 8; ++r) acc[r] = fmaf(sWf[r][hh], x, acc[r]);
    }
    #pragma unroll
    for (int r = 0; r < 8; ++r)
        part[((size_t)blockIdx.y << 16) + (o0 + r) * 256 + t] = acc[r];
}

// ---- fold, stage 2: reduce partials, fp16 hi, compute bc --------------------
__global__ void fold_reduce_kernel(const float* __restrict__ part,
                                   const float* __restrict__ Wf,
                                   const float* __restrict__ bo1,
                                   const float* __restrict__ bfb,
                                   __half* __restrict__ Wch,
                                   float* __restrict__ bc) {
    const int o = blockIdx.x, t = threadIdx.x;
    float v = 0.f;
    #pragma unroll
    for (int kz = 0; kz < 8; ++kz) v += part[((size_t)kz << 16) + o * 256 + t];
    Wch[o * 256 + t] = __float2half_rn(v);

    __shared__ float red[256];
    red[t] = Wf[o * 256 + t] * bo1[t];
    __syncthreads();
    #pragma unroll
    for (int s = 128; s > 0; s >>= 1) {
        if (t < s) red[t] += red[t + s];
        __syncthreads();
    }
    if (t == 0) bc[o] = red[0] + bfb[o];
}

// ---------------- pipelined mma.sync GEMM ------------------------------------
// C[M, 128 cols @ ncol0] = act(A @ W^T + bias). fp16 operands, fp32 accum.
// PASSES=3: STAGES=2, arrays {Ah,Al,Bh,Bl}; PASSES=1: STAGES=4, arrays {Ah,Bh}.
// Both configs: 82KB dynamic smem -> 2 CTAs/SM (occupancy doubling vs R7).
// Block 256 thr (8 warps: 2M x 4N), tile 128x128x32, row stride 80B.

template<int PASSES, bool GATHER, bool RELU>
__global__ void __launch_bounds__(256, 2)
gemm2(const __half* __restrict__ Ah, const __half* __restrict__ Al,
      const __half* __restrict__ Wh, const __half* __restrict__ Wl,
      const float* __restrict__ bias, float* __restrict__ C,
      int Mtiles) {
    constexpr int ARR    = (PASSES == 3) ? 4 : 2;   // smem arrays per stage
    constexpr int NA     = (PASSES == 3) ? 2 : 1;   // A arrays
    constexpr int STAGES = (PASSES == 3) ? 2 : 4;
    constexpr uint32_t STG = ARR * 10240;

    extern __shared__ char smem[];
    const uint32_t sb = smem_u32(smem);
    float* sbias = (float*)(smem + STAGES * STG);
    const int t = threadIdx.x, lane = t & 31, wid = t >> 5;

    const int y   = blockIdx.x & 1;
    const int tb  = blockIdx.x >> 1;
    const int NTB = gridDim.x >> 1;
    const int ncol0 = y * 128;

    if (t < 128) sbias[t] = bias[ncol0 + t];

    int tiles = 0;
    for (int mt = tb; mt < Mtiles; mt += NTB) ++tiles;
    const int QS = tiles * 8;

    auto cp_stage = [&](int q) {
        const int lt = q >> 3, kt = q & 7;
        const int mt = tb + lt * NTB;
        const uint32_t db = sb + (uint32_t)(q & (STAGES - 1)) * STG;
        #pragma unroll
        for (int u = 0; u < ARR * 2; ++u) {
            const int s = t + (u << 8);
            const int id  = s >> 9;           // array index 0..ARR-1
            const int row = (s >> 2) & 127;
            const int seg = s & 3;
            const uint32_t dst = db + (uint32_t)(id * 10240 + row * 80 + seg * 16);
            const __half* src;
            if (id < NA) {                    // A arrays (0=hi, 1=lo)
                int g = mt * 128 + row;
                if (GATHER) g = (g >> 2) * 12 + 3 * (g & 3);
                src = (id ? Al : Ah) + (size_t)g * 256 + kt * 32 + seg * 8;
            } else {                          // B arrays (0=hi, 1=lo)
                src = ((id - NA) ? Wl : Wh) + (ncol0 + row) * 256 + kt * 32 + seg * 8;
            }
            cp16(dst, src);
        }
        asm volatile("cp.async.commit_group;\n" ::: "memory");
    };

    const int wm = (wid & 1) * 64;
    const int wn = (wid >> 1) * 32;
    const uint32_t aoff = (uint32_t)((wm + (lane & 15)) * 80 + ((lane >> 4) << 4));
    const uint32_t boff = (uint32_t)((lane & 7) * 80 + (((lane >> 3) & 1) << 4));

    float c[4][4][4];
    #pragma unroll
    for (int i = 0; i < 4; ++i)
        #pragma unroll
        for (int j = 0; j < 4; ++j)
            #pragma unroll
            for (int e = 0; e < 4; ++e) c[i][j][e] = 0.f;

    const int npre = QS < (STAGES - 1) ? QS : (STAGES - 1);
    for (int q = 0; q < npre; ++q) cp_stage(q);

    for (int q = 0; q < QS; ++q) {
        const int kt = q & 7;
        if constexpr (STAGES == 2)
            asm volatile("cp.async.wait_group 0;\n" ::: "memory");
        else
            asm volatile("cp.async.wait_group 2;\n" ::: "memory");
        __syncthreads();
        if (q + STAGES - 1 < QS) cp_stage(q + STAGES - 1);

        {
            const uint32_t ab     = sb + (uint32_t)(q & (STAGES - 1)) * STG;
            const uint32_t albase = ab + 10240;             // valid if PASSES==3
            const uint32_t bhbase = ab + NA * 10240;
            const uint32_t blbase = bhbase + 10240;         // valid if PASSES==3
            #pragma unroll
            for (int ks = 0; ks < 32; ks += 16) {
                uint32_t rbh[4][2], rah[4][4];
                #pragma unroll
                for (int j = 0; j < 4; ++j) {
                    const uint32_t o = boff + (uint32_t)((wn + 8 * j) * 80 + ks * 2);
                    ldmatrix_x2(rbh[j][0], rbh[j][1], bhbase + o);
                }
                #pragma unroll
                for (int i = 0; i < 4; ++i) {
                    const uint32_t o = aoff + (uint32_t)(i * 16 * 80 + ks * 2);
                    ldmatrix_x4(rah[i][0], rah[i][1], rah[i][2], rah[i][3], ab + o);
                }
                // pass 1: hi*hi
                #pragma unroll
                for (int i = 0; i < 4; ++i)
                    #pragma unroll
                    for (int j = 0; j < 4; ++j)
                        mma_f16(c[i][j], rah[i][0], rah[i][1], rah[i][2], rah[i][3],
                                rbh[j][0], rbh[j][1]);
                if constexpr (PASSES == 3) {
                    uint32_t rbl[4][2], ral[4][4];
                    #pragma unroll
                    for (int j = 0; j < 4; ++j) {
                        const uint32_t o = boff + (uint32_t)((wn + 8 * j) * 80 + ks * 2);
                        ldmatrix_x2(rbl[j][0], rbl[j][1], blbase + o);
                    }
                    #pragma unroll
                    for (int i = 0; i < 4; ++i) {
                        const uint32_t o = aoff + (uint32_t)(i * 16 * 80 + ks * 2);
                        ldmatrix_x4(ral[i][0], ral[i][1], ral[i][2], ral[i][3], albase + o);
                    }
                    // pass 2: hi*lo
                    #pragma unroll
                    for (int i = 0; i < 4; ++i)
                        #pragma unroll
                        for (int j = 0; j < 4; ++j)
                            mma_f16(c[i][j], rah[i][0], rah[i][1], rah[i][2], rah[i][3],
                                    rbl[j][0], rbl[j][1]);
                    // pass 3: lo*hi
                    #pragma unroll
                    for (int i = 0; i < 4; ++i)
                        #pragma unroll
                        for (int j = 0; j < 4; ++j)
                            mma_f16(c[i][j], ral[i][0], ral[i][1], ral[i][2], ral[i][3],
                                    rbh[j][0], rbh[j][1]);
                }
            }
        }

        if (kt == 7) {
            const int mt = tb + (q >> 3) * NTB;
            const int gr = lane >> 2, gc = (lane & 3) * 2;
            const int mbase = mt * 128 + wm;
            #pragma unroll
            for (int i = 0; i < 4; ++i) {
                #pragma unroll
                for (int j = 0; j < 4; ++j) {
                    const int col = wn + 8 * j + gc;
                    const float b0v = sbias[col], b1v = sbias[col + 1];
                    float v0 = c[i][j][0] + b0v, v1 = c[i][j][1] + b1v;
                    float v2 = c[i][j][2] + b0v, v3 = c[i][j][3] + b1v;
                    if (RELU) {
                        v0 = fmaxf(v0, 0.f); v1 = fmaxf(v1, 0.f);
                        v2 = fmaxf(v2, 0.f); v3 = fmaxf(v3, 0.f);
                    }
                    const int r0 = mbase + 16 * i + gr;
                    *(float2*)&C[(size_t)r0 * 256 + ncol0 + col]       = make_float2(v0, v1);
                    *(float2*)&C[(size_t)(r0 + 8) * 256 + ncol0 + col] = make_float2(v2, v3);
                    c[i][j][0] = 0.f; c[i][j][1] = 0.f;
                    c[i][j][2] = 0.f; c[i][j][3] = 0.f;
                }
            }
        }
    }
}

// ---------------- attention ---------------------------------------------------
// block = 128 thr = one batch; warp w -> sel row (node 3w). f1 written fp16.
__global__ void __launch_bounds__(128)
attn_kernel(const float* __restrict__ q1, const float* __restrict__ k1,
            const float* __restrict__ wh1, const float* __restrict__ label,
            const float* __restrict__ adj, __half* __restrict__ f1h) {
    __shared__ float sk [NNODE * 256];
    __shared__ float swh[NNODE * 256];
    __shared__ float sq [4 * 256];
    __shared__ float sadj[4 * NNODE];
    __shared__ float slab[NNODE];

    const int b = blockIdx.x, t = threadIdx.x;

    const float4* k4 = (const float4*)(k1  + (size_t)b * NNODE * 256);
    const float4* w4 = (const float4*)(wh1 + (size_t)b * NNODE * 256);
    const float4* q4 = (const float4*)(q1  + (size_t)b * 4 * 256);
    float4* dk = (float4*)sk;
    float4* dw = (float4*)swh;
    float4* dq = (float4*)sq;
    #pragma unroll
    for (int u = 0; u < 6; ++u) { dk[t + 128 * u] = k4[t + 128 * u];
                                  dw[t + 128 * u] = w4[t + 128 * u]; }
    #pragma unroll
    for (int u = 0; u < 2; ++u)   dq[t + 128 * u] = q4[t + 128 * u];
    if (t < NNODE) slab[t] = label[b * NNODE + t];
    if (t < 4 * NNODE) {
        int i = t / NNODE, m = t % NNODE;
        sadj[t] = adj[(3 * i) * NNODE + m];
    }
    __syncthreads();

    const int w = t >> 5, l = t & 31;
    float qv[8];
    {
        const float4* qp = (const float4*)(sq + w * 256 + l * 8);
        float4 a = qp[0], bq_ = qp[1];
        qv[0]=a.x; qv[1]=a.y; qv[2]=a.z; qv[3]=a.w;
        qv[4]=bq_.x; qv[5]=bq_.y; qv[6]=bq_.z; qv[7]=bq_.w;
    }
    float s[NNODE];
    #pragma unroll
    for (int m = 0; m < NNODE; ++m) {
        const float4* kp = (const float4*)(sk + m * 256 + l * 8);
        float4 a = kp[0], bb = kp[1];
        s[m] = qv[0]*a.x + qv[1]*a.y + qv[2]*a.z + qv[3]*a.w
             + qv[4]*bb.x + qv[5]*bb.y + qv[6]*bb.z + qv[7]*bb.w;
    }
    #pragma unroll
    for (int m = 0; m < NNODE; ++m)
        #pragma unroll
        for (int off = 16; off > 0; off >>= 1)
            s[m] += __shfl_xor_sync(0xffffffffu, s[m], off);

    float mx = -3.0e38f;
    #pragma unroll
    for (int m = 0; m < NNODE; ++m) {
        float sm = (sadj[w * NNODE + m] > 0.5f) ? s[m] : -9.0e15f;
        s[m] = sm;
        mx = fmaxf(mx, sm);
    }
    float sum = 0.f;
    #pragma unroll
    for (int m = 0; m < NNODE; ++m) { float p = expf(s[m] - mx); s[m] = p; sum += p; }
    const float inv = 1.f / sum;
    #pragma unroll
    for (int m = 0; m < NNODE; ++m) s[m] = s[m] * inv * slab[m];

    float o[8] = {0,0,0,0,0,0,0,0};
    #pragma unroll
    for (int m = 0; m < NNODE; ++m) {
        const float4* wp = (const float4*)(swh + m * 256 + l * 8);
        float4 a = wp[0], bb = wp[1];
        float am = s[m];
        o[0] = fmaf(am, a.x, o[0]); o[1] = fmaf(am, a.y, o[1]);
        o[2] = fmaf(am, a.z, o[2]); o[3] = fmaf(am, a.w, o[3]);
        o[4] = fmaf(am, bb.x, o[4]); o[5] = fmaf(am, bb.y, o[5]);
        o[6] = fmaf(am, bb.z, o[6]); o[7] = fmaf(am, bb.w, o[7]);
    }
    uint32_t pk[4];
    #pragma unroll
    for (int g = 0; g < 4; ++g) {
        __half2 h2 = __floats2half2_rn(o[2*g], o[2*g+1]);
        pk[g] = *(uint32_t*)&h2;
    }
    const size_t idx = (size_t)(b * 4 + w) * 256 + l * 8;
    *(uint4*)(f1h + idx) = make_uint4(pk[0], pk[1], pk[2], pk[3]);
}

// ---------------- host launch -------------------------------------------------
extern "C" void kernel_launch(void* const* d_in, const int* in_sizes, int n_in,
                              void* d_out, int out_size) {
    const float* h     = (const float*)d_in[0];
    const float* adj   = (const float*)d_in[1];
    const float* label = (const float*)d_in[2];
    const float* Wv    = (const float*)d_in[3];
    const float* bv    = (const float*)d_in[4];
    const float* Wk    = (const float*)d_in[5];
    const float* bk    = (const float*)d_in[6];
    const float* Wq    = (const float*)d_in[7];
    const float* bq    = (const float*)d_in[8];
    const float* Wo1   = (const float*)d_in[9];
    const float* bo1   = (const float*)d_in[10];
    const float* Wf    = (const float*)d_in[11];
    const float* bf    = (const float*)d_in[12];
    float* out = (float*)d_out;

    float *p_Wh1, *p_k1, *p_q1, *p_bc, *p_part;
    __half *p_hh, *p_hl, *p_f1h;
    __half *p_Wvh, *p_Wvl, *p_Wkh, *p_Wkl, *p_Wqh, *p_Wql, *p_Wch;
    cudaGetSymbolAddress((void**)&p_Wh1, g_Wh1);
    cudaGetSymbolAddress((void**)&p_k1,  g_k1);
    cudaGetSymbolAddress((void**)&p_q1,  g_q1);
    cudaGetSymbolAddress((void**)&p_bc,  g_bc);
    cudaGetSymbolAddress((void**)&p_part, g_Wc_part);
    cudaGetSymbolAddress((void**)&p_hh,  g_hh);
    cudaGetSymbolAddress((void**)&p_hl,  g_hl);
    cudaGetSymbolAddress((void**)&p_f1h, g_f1h);
    cudaGetSymbolAddress((void**)&p_Wvh, g_Wv_h);
    cudaGetSymbolAddress((void**)&p_Wvl, g_Wv_l);
    cudaGetSymbolAddress((void**)&p_Wkh, g_Wk_h);
    cudaGetSymbolAddress((void**)&p_Wkl, g_Wk_l);
    cudaGetSymbolAddress((void**)&p_Wqh, g_Wq_h);
    cudaGetSymbolAddress((void**)&p_Wql, g_Wq_l);
    cudaGetSymbolAddress((void**)&p_Wch, g_Wc_h);

    const int SMEM3 = 2 * 40960 + 1024;   // 2-stage fp16x3 -> 2 CTAs/SM
    const int SMEM1 = 4 * 20480 + 1024;   // 4-stage fp16x1 -> 2 CTAs/SM
    cudaFuncSetAttribute(gemm2<3, false, true>,
                         cudaFuncAttributeMaxDynamicSharedMemorySize, SMEM3);
    cudaFuncSetAttribute(gemm2<3, true, true>,
                         cudaFuncAttributeMaxDynamicSharedMemorySize, SMEM3);
    cudaFuncSetAttribute(gemm2<1, false, true>,
                         cudaFuncAttributeMaxDynamicSharedMemorySize, SMEM1);
    cudaFuncSetAttribute(gemm2<1, false, false>,
                         cudaFuncAttributeMaxDynamicSharedMemorySize, SMEM1);

    // Launch order keeps the big K-GEMM at index 4 (the launch ncu captures).
    convert_h_kernel<<<12288, 256>>>(h, p_hh, p_hl);             // 1
    convert_w_kernel<<<256, 256>>>(Wv, p_Wvh, p_Wvl);            // 2
    convert_w_kernel<<<256, 256>>>(Wk, p_Wkh, p_Wkl);            // 3
    // K GEMM (fp16x3): k1 = relu(h@Wk^T + bk)                   // 4
    gemm2<3, false, true><<<296, 256, SMEM3>>>(
        p_hh, p_hl, p_Wkh, p_Wkl, bk, p_k1, M_VK / 128);
    // V GEMM (fp16x1): Wh1 = relu(h@Wv^T + bv)                  // 5
    gemm2<1, false, true><<<296, 256, SMEM1>>>(
        p_hh, nullptr, p_Wvh, nullptr, bv, p_Wh1, M_VK / 128);
    convert_w_kernel<<<256, 256>>>(Wq, p_Wqh, p_Wql);            // 6
    // Q GEMM (fp16x3, gathered): q1 = relu(h_sel@Wq^T + bq)     // 7
    gemm2<3, true, true><<<296, 256, SMEM3>>>(
        p_hh, p_hl, p_Wqh, p_Wql, bq, p_q1, M_SEL / 128);
    fold_part_kernel<<<dim3(32, 8), 256>>>(Wf, Wo1, p_part);     // 8
    fold_reduce_kernel<<<256, 256>>>(p_part, Wf, bo1, bf, p_Wch, p_bc);  // 9
    attn_kernel<<<BATCH, 128>>>(p_q1, p_k1, p_Wh1, label, adj, p_f1h);   // 10
    // out GEMM (fp16x1) straight into d_out                     // 11
    gemm2<1, false, false><<<296, 256, SMEM1>>>(
        p_f1h, nullptr, p_Wch, nullptr, p_bc, out, M_SEL / 128);
}